// round 1
// baseline (speedup 1.0000x reference)
#include <cuda_runtime.h>

#define SDIM   128
#define MUL1   64
#define D1     3
#define MUL2   32
#define D2     5
#define DIM    480           // 128 + 64*3 + 32*5
#define NVEC   120           // DIM/4 float4 per row
#define EPS    1e-5f

__global__ __launch_bounds__(128) void eln_kernel(
    const float* __restrict__ x,
    const float* __restrict__ weight,
    const float* __restrict__ bias,
    float* __restrict__ out)
{
    __shared__ float row[DIM];
    __shared__ float red[8];     // 4 warp sums + 4 warp sumsqs
    __shared__ float stats[2];   // mean, rinv

    const int tid = threadIdx.x;
    const long long base = (long long)blockIdx.x * DIM;

    // ---- vectorized coalesced load: 120 x float4 ----
    const float4* __restrict__ xin = (const float4*)(x + base);
    if (tid < NVEC) ((float4*)row)[tid] = xin[tid];
    __syncthreads();

    // ---- scalar layernorm stats (all 128 threads, one value each) ----
    const float s = row[tid];
    float sum = s, sq = s * s;
    #pragma unroll
    for (int o = 16; o; o >>= 1) {
        sum += __shfl_xor_sync(0xFFFFFFFFu, sum, o);
        sq  += __shfl_xor_sync(0xFFFFFFFFu, sq,  o);
    }
    const int w = tid >> 5;
    if ((tid & 31) == 0) { red[w] = sum; red[4 + w] = sq; }
    __syncthreads();

    if (tid == 0) {
        float ts = red[0] + red[1] + red[2] + red[3];
        float tq = red[4] + red[5] + red[6] + red[7];
        float m  = ts * (1.0f / 128.0f);
        float var = tq * (1.0f / 128.0f) - m * m;
        stats[0] = m;
        stats[1] = rsqrtf(var + EPS);
    }

    // ---- segment norms, in place (each thread owns disjoint smem) ----
    if (tid < MUL1) {
        // segment of 3 at row[128 + 3*tid]
        float* p = &row[SDIM + D1 * tid];
        float a = p[0], b = p[1], c = p[2];
        float m = (a + b + c) * (1.0f / 3.0f);
        float da = a - m, db = b - m, dc = c - m;
        float var = (da * da + db * db + dc * dc) * (1.0f / 3.0f);
        float r = rsqrtf(var + EPS);
        p[0] = da * r; p[1] = db * r; p[2] = dc * r;
    } else if (tid < MUL1 + MUL2) {
        // segment of 5 at row[320 + 5*(tid-64)]
        float* p = &row[SDIM + MUL1 * D1 + D2 * (tid - MUL1)];
        float a = p[0], b = p[1], c = p[2], d = p[3], e = p[4];
        float m = (a + b + c + d + e) * (1.0f / 5.0f);
        float da = a - m, db = b - m, dc = c - m, dd = d - m, de = e - m;
        float var = (da * da + db * db + dc * dc + dd * dd + de * de) * (1.0f / 5.0f);
        float r = rsqrtf(var + EPS);
        p[0] = da * r; p[1] = db * r; p[2] = dc * r; p[3] = dd * r; p[4] = de * r;
    }
    __syncthreads();

    // ---- scalar normalized value with affine ----
    const float m = stats[0], rinv = stats[1];
    row[tid] = (s - m) * rinv * __ldg(&weight[tid]) + __ldg(&bias[tid]);
    __syncthreads();

    // ---- vectorized coalesced store ----
    float4* __restrict__ xout = (float4*)(out + base);
    if (tid < NVEC) xout[tid] = ((float4*)row)[tid];
}

extern "C" void kernel_launch(void* const* d_in, const int* in_sizes, int n_in,
                              void* d_out, int out_size)
{
    const float* x      = (const float*)d_in[0];
    const float* weight = (const float*)d_in[1];
    const float* bias   = (const float*)d_in[2];
    float* out = (float*)d_out;

    const int n_rows = in_sizes[0] / DIM;   // 262144
    eln_kernel<<<n_rows, 128>>>(x, weight, bias, out);
}

// round 2
// speedup vs baseline: 1.0909x; 1.0909x over previous
#include <cuda_runtime.h>

#define SDIM   128
#define MUL1   64
#define D1     3
#define MUL2   32
#define D2     5
#define VDIM   352           // 64*3 + 32*5
#define DIM    480           // 128 + VDIM
#define NV4    88            // VDIM/4 float4 per row (vector region)
#define EPS    1e-5f

__global__ __launch_bounds__(128) void eln_kernel(
    const float* __restrict__ x,
    const float* __restrict__ weight,
    const float* __restrict__ bias,
    float* __restrict__ out)
{
    __shared__ float vec[VDIM];
    __shared__ float red[8];     // 4 warp sums + 4 warp sumsqs

    const int tid = threadIdx.x;
    const long long base = (long long)blockIdx.x * DIM;

    // ---- issue all global loads up front ----
    // scalar element (coalesced 32-bit)
    const float s = x[base + tid];
    // vector region staged through smem (coalesced float4, threads 0..87)
    const float4* __restrict__ xin = (const float4*)(x + base + SDIM);
    float4 v;
    if (tid < NV4) v = xin[tid];

    // ---- scalar layernorm stats (warp shuffle + smem partials) ----
    float sum = s, sq = s * s;
    #pragma unroll
    for (int o = 16; o; o >>= 1) {
        sum += __shfl_xor_sync(0xFFFFFFFFu, sum, o);
        sq  += __shfl_xor_sync(0xFFFFFFFFu, sq,  o);
    }
    if ((tid & 31) == 0) { red[tid >> 5] = sum; red[4 + (tid >> 5)] = sq; }
    if (tid < NV4) ((float4*)vec)[tid] = v;
    __syncthreads();

    // all threads combine partials redundantly (no extra barrier)
    const float ts = red[0] + red[1] + red[2] + red[3];
    const float tq = red[4] + red[5] + red[6] + red[7];
    const float m  = ts * (1.0f / 128.0f);
    const float rinv = rsqrtf(tq * (1.0f / 128.0f) - m * m + EPS);

    // ---- scalar output: straight to global, overlaps with segment work ----
    out[base + tid] = (s - m) * rinv * __ldg(&weight[tid]) + __ldg(&bias[tid]);

    // ---- segment norms in smem (disjoint per-thread regions) ----
    if (tid < MUL1) {
        float* p = &vec[D1 * tid];
        float a = p[0], b = p[1], c = p[2];
        float sm = (a + b + c) * (1.0f / 3.0f);
        float da = a - sm, db = b - sm, dc = c - sm;
        float r = rsqrtf((da * da + db * db + dc * dc) * (1.0f / 3.0f) + EPS);
        p[0] = da * r; p[1] = db * r; p[2] = dc * r;
    } else if (tid < MUL1 + MUL2) {
        float* p = &vec[MUL1 * D1 + D2 * (tid - MUL1)];
        float a = p[0], b = p[1], c = p[2], d = p[3], e = p[4];
        float sm = (a + b + c + d + e) * (1.0f / 5.0f);
        float da = a - sm, db = b - sm, dc = c - sm, dd = d - sm, de = e - sm;
        float r = rsqrtf((da * da + db * db + dc * dc + dd * dd + de * de) * (1.0f / 5.0f) + EPS);
        p[0] = da * r; p[1] = db * r; p[2] = dc * r; p[3] = dd * r; p[4] = de * r;
    }
    __syncthreads();

    // ---- vector region store (coalesced float4) ----
    float4* __restrict__ xout = (float4*)(out + base + SDIM);
    if (tid < NV4) xout[tid] = ((float4*)vec)[tid];
}

extern "C" void kernel_launch(void* const* d_in, const int* in_sizes, int n_in,
                              void* d_out, int out_size)
{
    const float* x      = (const float*)d_in[0];
    const float* weight = (const float*)d_in[1];
    const float* bias   = (const float*)d_in[2];
    float* out = (float*)d_out;

    const int n_rows = in_sizes[0] / DIM;   // 262144
    eln_kernel<<<n_rows, 128>>>(x, weight, bias, out);
}

// round 3
// speedup vs baseline: 1.1976x; 1.0978x over previous
#include <cuda_runtime.h>

#define SDIM   128
#define MUL1   64
#define D1     3
#define MUL2   32
#define D2     5
#define VDIM   352           // 64*3 + 32*5
#define DIM    480           // 128 + VDIM
#define NV4    88            // VDIM/4 float4 per row (vector region)
#define EPS    1e-5f

__device__ __forceinline__ void seg_norm(float* __restrict__ vec, int tid)
{
    if (tid < MUL1) {
        float* p = &vec[D1 * tid];
        float a = p[0], b = p[1], c = p[2];
        float sm = (a + b + c) * (1.0f / 3.0f);
        float da = a - sm, db = b - sm, dc = c - sm;
        float r = rsqrtf((da * da + db * db + dc * dc) * (1.0f / 3.0f) + EPS);
        p[0] = da * r; p[1] = db * r; p[2] = dc * r;
    } else if (tid < MUL1 + MUL2) {
        float* p = &vec[MUL1 * D1 + D2 * (tid - MUL1)];
        float a = p[0], b = p[1], c = p[2], d = p[3], e = p[4];
        float sm = (a + b + c + d + e) * (1.0f / 5.0f);
        float da = a - sm, db = b - sm, dc = c - sm, dd = d - sm, de = e - sm;
        float r = rsqrtf((da * da + db * db + dc * dc + dd * dd + de * de) * (1.0f / 5.0f) + EPS);
        p[0] = da * r; p[1] = db * r; p[2] = dc * r; p[3] = dd * r; p[4] = de * r;
    }
}

__global__ __launch_bounds__(128) void eln_kernel(
    const float* __restrict__ x,
    const float* __restrict__ weight,
    const float* __restrict__ bias,
    float* __restrict__ out)
{
    __shared__ float vec0[VDIM];
    __shared__ float vec1[VDIM];
    __shared__ float red[16];    // [0..3] sum0 [4..7] sq0 [8..11] sum1 [12..15] sq1

    const int tid = threadIdx.x;
    const long long base0 = (long long)blockIdx.x * (2 * DIM);
    const long long base1 = base0 + DIM;

    // ---- batch ALL global loads for both rows up front (max MLP) ----
    const float w  = __ldg(&weight[tid]);
    const float bb = __ldg(&bias[tid]);
    const float s0 = x[base0 + tid];
    const float s1 = x[base1 + tid];
    float4 v0, v1;
    const float4* __restrict__ xin0 = (const float4*)(x + base0 + SDIM);
    const float4* __restrict__ xin1 = (const float4*)(x + base1 + SDIM);
    if (tid < NV4) { v0 = xin0[tid]; v1 = xin1[tid]; }

    // ---- warp-level stats for both rows, interleaved ----
    float sum0 = s0, sq0 = s0 * s0;
    float sum1 = s1, sq1 = s1 * s1;
    #pragma unroll
    for (int o = 16; o; o >>= 1) {
        sum0 += __shfl_xor_sync(0xFFFFFFFFu, sum0, o);
        sq0  += __shfl_xor_sync(0xFFFFFFFFu, sq0,  o);
        sum1 += __shfl_xor_sync(0xFFFFFFFFu, sum1, o);
        sq1  += __shfl_xor_sync(0xFFFFFFFFu, sq1,  o);
    }
    const int w5 = tid >> 5;
    if ((tid & 31) == 0) {
        red[w5] = sum0; red[4 + w5] = sq0;
        red[8 + w5] = sum1; red[12 + w5] = sq1;
    }
    if (tid < NV4) {
        ((float4*)vec0)[tid] = v0;
        ((float4*)vec1)[tid] = v1;
    }
    __syncthreads();

    // ---- combine partials redundantly (no extra barrier) ----
    const float m0 = (red[0] + red[1] + red[2] + red[3]) * (1.0f / 128.0f);
    const float r0 = rsqrtf((red[4] + red[5] + red[6] + red[7]) * (1.0f / 128.0f) - m0 * m0 + EPS);
    const float m1 = (red[8] + red[9] + red[10] + red[11]) * (1.0f / 128.0f);
    const float r1 = rsqrtf((red[12] + red[13] + red[14] + red[15]) * (1.0f / 128.0f) - m1 * m1 + EPS);

    // ---- scalar outputs straight to global (overlaps segment work) ----
    out[base0 + tid] = (s0 - m0) * r0 * w + bb;
    out[base1 + tid] = (s1 - m1) * r1 * w + bb;

    // ---- segment norms for both rows (disjoint smem regions) ----
    seg_norm(vec0, tid);
    seg_norm(vec1, tid);
    __syncthreads();

    // ---- vector region stores (coalesced float4) ----
    float4* __restrict__ xout0 = (float4*)(out + base0 + SDIM);
    float4* __restrict__ xout1 = (float4*)(out + base1 + SDIM);
    if (tid < NV4) {
        xout0[tid] = ((float4*)vec0)[tid];
        xout1[tid] = ((float4*)vec1)[tid];
    }
}

extern "C" void kernel_launch(void* const* d_in, const int* in_sizes, int n_in,
                              void* d_out, int out_size)
{
    const float* x      = (const float*)d_in[0];
    const float* weight = (const float*)d_in[1];
    const float* bias   = (const float*)d_in[2];
    float* out = (float*)d_out;

    const int n_rows = in_sizes[0] / DIM;   // 262144
    eln_kernel<<<n_rows / 2, 128>>>(x, weight, bias, out);
}